// round 15
// baseline (speedup 1.0000x reference)
#include <cuda_runtime.h>
#include <cuda_fp16.h>
#include <stdint.h>

// Problem constants
#define ACT_DIM   2048
#define DICT_SIZE 32768
#define BATCH     4096
#define TOPK      256
#define CANDRANK  320   // nominal selection rank for coarse pass
#define CANDCAP   384   // storage cap (holds all threshold ties)
#define SORTN     512

// ---------------- scratch (device globals; no allocation allowed) ----------
__device__ __half g_feath[(size_t)BATCH * DICT_SIZE];  // 256 MB (fp16 coarse feat)
__device__ float  g_Wt[(size_t)DICT_SIZE * ACT_DIM];   // 256 MB (fp32, refine)
__device__ __half g_Wth[(size_t)DICT_SIZE * ACT_DIM];  // 128 MB (fp16: encode B + decode)
__device__ __half g_Ah[(size_t)BATCH * ACT_DIM];       // 16 MB (fp16 x - b_dec)
__device__ int    g_cand_i[(size_t)BATCH * CANDCAP];
__device__ int    g_cand_n[BATCH];
__device__ float  g_topv[(size_t)BATCH * TOPK];
__device__ int    g_topi[(size_t)BATCH * TOPK];

// ---------------- helpers ---------------------------------------------------
__device__ __forceinline__ uint32_t smem_u32(const void* p) {
    uint32_t a;
    asm("{ .reg .u64 t; cvta.to.shared.u64 t, %1; cvt.u32.u64 %0, t; }" : "=r"(a) : "l"(p));
    return a;
}
// XOR swizzle for 128-byte rows (8-row / 1KB atom)
#define SWZ(o) ((o) ^ (((o) >> 3) & 0x70))

__device__ __forceinline__ void cp_async16(uint32_t saddr, const void* gaddr) {
    asm volatile("cp.async.cg.shared.global [%0], [%1], 16;"
                 :: "r"(saddr), "l"(gaddr) : "memory");
}

// ---------------- kernel 0: A = fp16(x - b_dec) ----------------------------
__global__ __launch_bounds__(256)
void convert_x_kernel(const float* __restrict__ x, const float* __restrict__ bdec,
                      __half* __restrict__ Ah) {
    const int row = blockIdx.x;
    const int c0  = threadIdx.x * 8;
    const float* xr = x + (size_t)row * ACT_DIM + c0;
    float4 v1 = *(const float4*)(xr);
    float4 v2 = *(const float4*)(xr + 4);
    float4 b1 = *(const float4*)(bdec + c0);
    float4 b2 = *(const float4*)(bdec + c0 + 4);
    __half2 h0 = __floats2half2_rn(v1.x - b1.x, v1.y - b1.y);
    __half2 h1 = __floats2half2_rn(v1.z - b1.z, v1.w - b1.w);
    __half2 h2 = __floats2half2_rn(v2.x - b2.x, v2.y - b2.y);
    __half2 h3 = __floats2half2_rn(v2.z - b2.z, v2.w - b2.w);
    uint4 out;
    out.x = *(uint32_t*)&h0; out.y = *(uint32_t*)&h1;
    out.z = *(uint32_t*)&h2; out.w = *(uint32_t*)&h3;
    *(uint4*)(Ah + (size_t)row * ACT_DIM + c0) = out;
}

// ---------------- kernel 1: transpose W -> Wt (fp32) + Wth (fp16) ----------
__global__ void transpose_kernel(const float* __restrict__ W, float* __restrict__ Wt,
                                 __half* __restrict__ Wth) {
    __shared__ float tile[32][33];
    const int x0 = blockIdx.x * 32;
    const int y0 = blockIdx.y * 32;
    const int tx = threadIdx.x;
    const int ty = threadIdx.y;
    #pragma unroll
    for (int i = 0; i < 32; i += 8)
        tile[ty + i][tx] = W[(size_t)(y0 + ty + i) * DICT_SIZE + x0 + tx];
    __syncthreads();
    #pragma unroll
    for (int i = 0; i < 32; i += 8) {
        const float v = tile[tx][ty + i];
        const size_t o = (size_t)(x0 + ty + i) * ACT_DIM + y0 + tx;
        Wt[o] = v;
        Wth[o] = __float2half(v);
    }
}

// ---------------- kernel 2: fp16 HMMA encode GEMM (fp32 accumulators) ------
// CTA tile 128x128x64, 8 warps 2Mx4N, 3-stage cp.async ring, 1 barrier/iter.
// (R13 champion configuration — fp16-acc tested in R14, rate parity, reverted.)
#define EBM 128
#define EBN 128
#define EBK 64
#define EKITERS (ACT_DIM / EBK)   // 32
#define ESTAGE  32768
#define ENC_SMEM (3 * ESTAGE + 1024)

__global__ __launch_bounds__(256, 2)
void encode_gemm_mma(const __half* __restrict__ Ah,
                     const __half* __restrict__ Bh,
                     __half* __restrict__ feat) {
    extern __shared__ unsigned char dsm[];
    const uint32_t raw  = smem_u32(dsm);
    const uint32_t base = (raw + 1023u) & ~1023u;

    const int tid  = threadIdx.x;
    const int lane = tid & 31;
    const int warp = tid >> 5;
    const int wm   = warp & 1;
    const int wn   = warp >> 1;
    const int Mbase = blockIdx.x * EBM;   // grid.x = M (32)
    const int Nbase = blockIdx.y * EBN;   // grid.y = N (256)

    float acc[4][4][4];
    #pragma unroll
    for (int a = 0; a < 4; a++)
        #pragma unroll
        for (int b = 0; b < 4; b++)
            #pragma unroll
            for (int c = 0; c < 4; c++) acc[a][b][c] = 0.0f;

    const int aRow = wm * 64 + ((lane >> 3) & 1) * 8 + (lane & 7);
    const int ah   = (lane >> 4) & 1;
    const int bRow = wn * 32 + ((lane >> 4) & 1) * 8 + (lane & 7);
    const int bh   = (lane >> 3) & 1;

#define LOAD_STAGE(SLOT, K0)                                                      \
    do {                                                                          \
        const uint32_t aBase = base + (SLOT) * ESTAGE;                            \
        const uint32_t bBase = aBase + 16384u;                                    \
        _Pragma("unroll")                                                         \
        for (int i = 0; i < 4; i++) {                                             \
            const int id = tid + i * 256;                                         \
            const int row = id >> 3, c16 = id & 7;                                \
            cp_async16(aBase + SWZ(row * 128 + c16 * 16),                         \
                       Ah + (size_t)(Mbase + row) * ACT_DIM + (K0) + c16 * 8);    \
        }                                                                         \
        _Pragma("unroll")                                                         \
        for (int i = 0; i < 4; i++) {                                             \
            const int id = tid + i * 256;                                         \
            const int row = id >> 3, c16 = id & 7;                                \
            cp_async16(bBase + SWZ(row * 128 + c16 * 16),                         \
                       Bh + (size_t)(Nbase + row) * ACT_DIM + (K0) + c16 * 8);    \
        }                                                                         \
        asm volatile("cp.async.commit_group;" ::: "memory");                      \
    } while (0)

    LOAD_STAGE(0, 0);
    LOAD_STAGE(1, EBK);

    int slot = 0;
    for (int s = 0; s < EKITERS; s++) {
        if (s + 2 < EKITERS) {
            asm volatile("cp.async.wait_group 1;" ::: "memory");
        } else {
            asm volatile("cp.async.wait_group 0;" ::: "memory");
        }
        __syncthreads();
        if (s + 2 < EKITERS) LOAD_STAGE((slot + 2) % 3, (s + 2) * EBK);

        const uint32_t cA = base + slot * ESTAGE;
        const uint32_t cB = cA + 16384u;

        #pragma unroll
        for (int kk = 0; kk < 4; kk++) {
            uint32_t af[4][4];
            uint32_t bfr[2][4];
            #pragma unroll
            for (int mt = 0; mt < 4; mt++) {
                const uint32_t addr = cA + SWZ((aRow + mt * 16) * 128 + (kk * 2 + ah) * 16);
                asm volatile("ldmatrix.sync.aligned.m8n8.x4.shared.b16 {%0,%1,%2,%3}, [%4];"
                             : "=r"(af[mt][0]), "=r"(af[mt][1]), "=r"(af[mt][2]), "=r"(af[mt][3])
                             : "r"(addr));
            }
            #pragma unroll
            for (int np = 0; np < 2; np++) {
                const uint32_t addr = cB + SWZ((bRow + np * 16) * 128 + (kk * 2 + bh) * 16);
                asm volatile("ldmatrix.sync.aligned.m8n8.x4.shared.b16 {%0,%1,%2,%3}, [%4];"
                             : "=r"(bfr[np][0]), "=r"(bfr[np][1]), "=r"(bfr[np][2]), "=r"(bfr[np][3])
                             : "r"(addr));
            }
            #pragma unroll
            for (int mt = 0; mt < 4; mt++) {
                #pragma unroll
                for (int nt = 0; nt < 4; nt++) {
                    const uint32_t b0 = bfr[nt >> 1][(nt & 1) * 2];
                    const uint32_t b1 = bfr[nt >> 1][(nt & 1) * 2 + 1];
                    asm volatile(
                        "mma.sync.aligned.m16n8k16.row.col.f32.f16.f16.f32 "
                        "{%0,%1,%2,%3}, {%4,%5,%6,%7}, {%8,%9}, {%0,%1,%2,%3};"
                        : "+f"(acc[mt][nt][0]), "+f"(acc[mt][nt][1]),
                          "+f"(acc[mt][nt][2]), "+f"(acc[mt][nt][3])
                        : "r"(af[mt][0]), "r"(af[mt][1]), "r"(af[mt][2]), "r"(af[mt][3]),
                          "r"(b0), "r"(b1));
                }
            }
        }
        slot = (slot + 1) % 3;
    }
#undef LOAD_STAGE

    const int g  = lane >> 2;
    const int tg = lane & 3;
    #pragma unroll
    for (int mt = 0; mt < 4; mt++) {
        #pragma unroll
        for (int nt = 0; nt < 4; nt++) {
            const int r0 = Mbase + wm * 64 + mt * 16 + g;
            const int c  = Nbase + wn * 32 + nt * 8 + tg * 2;
            __half2 p0 = __floats2half2_rn(acc[mt][nt][0], acc[mt][nt][1]);
            __half2 p1 = __floats2half2_rn(acc[mt][nt][2], acc[mt][nt][3]);
            *(uint32_t*)(feat + (size_t)r0 * DICT_SIZE + c)       = *(uint32_t*)&p0;
            *(uint32_t*)(feat + (size_t)(r0 + 8) * DICT_SIZE + c) = *(uint32_t*)&p1;
        }
    }
}

// ---------------- kernel 3: per-row coarse top candidates (streaming radix)
__global__ __launch_bounds__(256)
void topk_kernel(const __half* __restrict__ feat,
                 int* __restrict__ candi, int* __restrict__ candn) {
    __shared__ unsigned int h0[8][128];
    __shared__ unsigned int hist[256];
    __shared__ unsigned int suf[256];
    __shared__ unsigned int sB0, sRem, sThr;
    __shared__ int gcnt, tcnt;
    __shared__ int tiebuf[64];

    const int row  = blockIdx.x;
    const int tid  = threadIdx.x;
    const int warp = tid >> 5;
    const uint4* src = (const uint4*)(feat + (size_t)row * DICT_SIZE);

    {
        unsigned int* hz = &h0[0][0];
        for (int i = tid; i < 8 * 128; i += 256) hz[i] = 0u;
    }
    if (tid == 0) { gcnt = 0; tcnt = 0; }
    __syncthreads();

    for (int i = tid; i < DICT_SIZE / 8; i += 256) {
        const uint4 v = src[i];
        #pragma unroll
        for (int q = 0; q < 4; q++) {
            const unsigned int u = (&v.x)[q];
            atomicAdd(&h0[warp][(u & 0x7FFFu) >> 8], 1u);
            atomicAdd(&h0[warp][((u >> 16) & 0x7FFFu) >> 8], 1u);
        }
    }
    __syncthreads();

    if (tid < 128) {
        unsigned int t = 0;
        #pragma unroll
        for (int w = 0; w < 8; w++) t += h0[w][tid];
        suf[tid] = t;
    }
    __syncthreads();
    for (int off = 1; off < 128; off <<= 1) {
        unsigned int v = 0;
        if (tid < 128 && tid + off < 128) v = suf[tid + off];
        __syncthreads();
        if (tid < 128) suf[tid] += v;
        __syncthreads();
    }
    if (tid < 128) {
        const unsigned int sufNext = (tid == 127) ? 0u : suf[tid + 1];
        if (suf[tid] >= CANDRANK && sufNext < CANDRANK) {
            sB0 = (unsigned int)tid;
            sRem = CANDRANK - sufNext;
        }
    }
    __syncthreads();
    const unsigned int b0sel = sB0;
    const unsigned int rem   = sRem;

    hist[tid] = 0u;
    __syncthreads();
    for (int i = tid; i < DICT_SIZE / 8; i += 256) {
        const uint4 v = src[i];
        #pragma unroll
        for (int q = 0; q < 4; q++) {
            const unsigned int u = (&v.x)[q];
            const unsigned int k0 = u & 0x7FFFu;
            const unsigned int k1 = (u >> 16) & 0x7FFFu;
            if ((k0 >> 8) == b0sel) atomicAdd(&hist[k0 & 255u], 1u);
            if ((k1 >> 8) == b0sel) atomicAdd(&hist[k1 & 255u], 1u);
        }
    }
    __syncthreads();
    suf[tid] = hist[tid];
    __syncthreads();
    for (int off = 1; off < 256; off <<= 1) {
        const unsigned int v = (tid + off < 256) ? suf[tid + off] : 0u;
        __syncthreads();
        suf[tid] += v;
        __syncthreads();
    }
    {
        const unsigned int sufNext = (tid == 255) ? 0u : suf[tid + 1];
        if (suf[tid] >= rem && sufNext < rem)
            sThr = (b0sel << 8) | (unsigned int)tid;
    }
    __syncthreads();
    const unsigned int thr = sThr;

    int* ti = candi + (size_t)row * CANDCAP;
    for (int i = tid; i < DICT_SIZE / 8; i += 256) {
        const uint4 v = src[i];
        #pragma unroll
        for (int q = 0; q < 4; q++) {
            const unsigned int u = (&v.x)[q];
            const unsigned int k0 = u & 0x7FFFu;
            const unsigned int k1 = (u >> 16) & 0x7FFFu;
            if (k0 > thr) {
                const int p = atomicAdd(&gcnt, 1);
                if (p < CANDCAP) ti[p] = i * 8 + q * 2;
            } else if (k0 == thr) {
                const int t = atomicAdd(&tcnt, 1);
                if (t < 64) tiebuf[t] = i * 8 + q * 2;
            }
            if (k1 > thr) {
                const int p = atomicAdd(&gcnt, 1);
                if (p < CANDCAP) ti[p] = i * 8 + q * 2 + 1;
            } else if (k1 == thr) {
                const int t = atomicAdd(&tcnt, 1);
                if (t < 64) tiebuf[t] = i * 8 + q * 2 + 1;
            }
        }
    }
    __syncthreads();
    const int ng = (gcnt < CANDCAP) ? gcnt : CANDCAP;
    const int nt = (tcnt < 64) ? tcnt : 64;
    if (tid < nt && ng + tid < CANDCAP) ti[ng + tid] = tiebuf[tid];
    if (tid == 0) {
        int tot = ng + nt;
        candn[row] = (tot < CANDCAP) ? tot : CANDCAP;
    }
}

// ---------------- kernel 4: fused refine (fp32 Wt, 4-acc ILP) + select -----
__global__ __launch_bounds__(512)
void refine_select_kernel(const float* __restrict__ x, const float* __restrict__ bdec,
                          const float* __restrict__ Wt, const int* __restrict__ candi,
                          const int* __restrict__ candn,
                          float* __restrict__ topv, int* __restrict__ topi) {
    __shared__ float sx[ACT_DIM];
    __shared__ int   sci[CANDCAP];
    __shared__ float srv[CANDCAP];
    __shared__ unsigned long long key[SORTN];
    __shared__ float val[SORTN];

    const int row  = blockIdx.x;
    const int tid  = threadIdx.x;     // 0..511
    const int lane = tid & 31;
    const int wid  = tid >> 5;        // 0..15
    const int n    = candn[row];

    const float* xr = x + (size_t)row * ACT_DIM;
    for (int i = tid; i < ACT_DIM; i += 512) sx[i] = xr[i] - bdec[i];
    for (int i = tid; i < CANDCAP; i += 512)
        sci[i] = (i < n) ? candi[(size_t)row * CANDCAP + i] : 0;
    __syncthreads();

    // 4-accumulator fp32 dot: breaks the 64-deep fmaf dependency chain.
    for (int c = wid; c < n; c += 16) {
        const float* wr = Wt + (size_t)sci[c] * ACT_DIM;
        float s0 = 0.f, s1 = 0.f, s2 = 0.f, s3 = 0.f;
        #pragma unroll
        for (int i = 0; i < 64; i += 4) {
            s0 = fmaf(sx[lane + 32 * (i + 0)], wr[lane + 32 * (i + 0)], s0);
            s1 = fmaf(sx[lane + 32 * (i + 1)], wr[lane + 32 * (i + 1)], s1);
            s2 = fmaf(sx[lane + 32 * (i + 2)], wr[lane + 32 * (i + 2)], s2);
            s3 = fmaf(sx[lane + 32 * (i + 3)], wr[lane + 32 * (i + 3)], s3);
        }
        float s = (s0 + s1) + (s2 + s3);
        #pragma unroll
        for (int off = 16; off > 0; off >>= 1)
            s += __shfl_down_sync(0xffffffffu, s, off);
        if (lane == 0) srv[c] = s;
    }
    __syncthreads();

    {
        const int i = tid;
        if (i < n) {
            const float v = srv[i];
            const unsigned int a = __float_as_uint(fabsf(v));
            key[i] = ((unsigned long long)(~a) << 32) |
                     (unsigned long long)(unsigned int)sci[i];
            val[i] = v;
        } else {
            key[i] = 0xFFFFFFFFFFFFFFFFull;
            val[i] = 0.0f;
        }
    }
    __syncthreads();

    for (int k = 2; k <= SORTN; k <<= 1) {
        for (int j = k >> 1; j > 0; j >>= 1) {
            const int i   = tid;
            const int ixj = i ^ j;
            if (ixj > i) {
                const bool up = ((i & k) == 0);
                const unsigned long long ki = key[i], kj = key[ixj];
                if ((ki > kj) == up) {
                    key[i] = kj; key[ixj] = ki;
                    const float vi = val[i];
                    val[i] = val[ixj]; val[ixj] = vi;
                }
            }
            __syncthreads();
        }
    }

    if (tid < TOPK) {
        topv[(size_t)row * TOPK + tid] = val[tid];
        topi[(size_t)row * TOPK + tid] = (int)(unsigned int)(key[tid] & 0xFFFFFFFFull);
    }
}

// ---------------- kernel 5: sparse gather decode (fp16 W: half traffic) ----
__global__ __launch_bounds__(512)
void decode_kernel(const __half* __restrict__ Wth,
                   const float* __restrict__ topv, const int* __restrict__ topi,
                   const float* __restrict__ bdec, float* __restrict__ out) {
    __shared__ float sval[TOPK];
    __shared__ int   sidx[TOPK];
    const int row = blockIdx.x;
    const int tid = threadIdx.x;   // 0..511

    if (tid < TOPK) {
        sval[tid] = topv[(size_t)row * TOPK + tid];
        sidx[tid] = topi[(size_t)row * TOPK + tid];
    }
    __syncthreads();

    float4 acc = make_float4(0.f, 0.f, 0.f, 0.f);
    const int c = tid * 4;
    #pragma unroll 4
    for (int k = 0; k < TOPK; k++) {
        const float v = sval[k];
        const uint2 w8 = *(const uint2*)(Wth + (size_t)sidx[k] * ACT_DIM + c);
        const __half2 h01 = *(const __half2*)&w8.x;
        const __half2 h23 = *(const __half2*)&w8.y;
        const float2 f01 = __half22float2(h01);
        const float2 f23 = __half22float2(h23);
        acc.x = fmaf(v, f01.x, acc.x);
        acc.y = fmaf(v, f01.y, acc.y);
        acc.z = fmaf(v, f23.x, acc.z);
        acc.w = fmaf(v, f23.y, acc.w);
    }
    const float4 b = *(const float4*)(bdec + c);
    acc.x += b.x; acc.y += b.y; acc.z += b.z; acc.w += b.w;
    *(float4*)(out + (size_t)row * ACT_DIM + c) = acc;
}

// ---------------- launch ---------------------------------------------------
extern "C" void kernel_launch(void* const* d_in, const int* in_sizes, int n_in,
                              void* d_out, int out_size) {
    const float* x    = (const float*)d_in[0];
    const float* W    = (const float*)d_in[1];
    const float* bdec = (const float*)d_in[2];
    float* out = (float*)d_out;

    __half *feath, *Wth, *Ah;
    float *Wt, *topv; int *candi, *candn, *topi;
    cudaGetSymbolAddress((void**)&feath, g_feath);
    cudaGetSymbolAddress((void**)&Wt,    g_Wt);
    cudaGetSymbolAddress((void**)&Wth,   g_Wth);
    cudaGetSymbolAddress((void**)&Ah,    g_Ah);
    cudaGetSymbolAddress((void**)&candi, g_cand_i);
    cudaGetSymbolAddress((void**)&candn, g_cand_n);
    cudaGetSymbolAddress((void**)&topv,  g_topv);
    cudaGetSymbolAddress((void**)&topi,  g_topi);

    convert_x_kernel<<<BATCH, 256>>>(x, bdec, Ah);
    {
        dim3 grid(DICT_SIZE / 32, ACT_DIM / 32);
        dim3 block(32, 8);
        transpose_kernel<<<grid, block>>>(W, Wt, Wth);
    }
    {
        cudaFuncSetAttribute(encode_gemm_mma,
                             cudaFuncAttributeMaxDynamicSharedMemorySize, ENC_SMEM);
        dim3 grid(BATCH / EBM, DICT_SIZE / EBN);   // x = M (32), y = N (256)
        encode_gemm_mma<<<grid, 256, ENC_SMEM>>>(Ah, Wth, feath);
    }
    topk_kernel<<<BATCH, 256>>>(feath, candi, candn);
    refine_select_kernel<<<BATCH, 512>>>(x, bdec, Wt, candi, candn, topv, topi);
    decode_kernel<<<BATCH, 512>>>(Wth, topv, topi, bdec, out);
}

// round 16
// speedup vs baseline: 1.0825x; 1.0825x over previous
#include <cuda_runtime.h>
#include <cuda_fp16.h>
#include <stdint.h>

// Problem constants
#define ACT_DIM   2048
#define DICT_SIZE 32768
#define BATCH     4096
#define TOPK      256
#define CANDRANK  288   // coarse selection rank (margin to rank-256 ~50 sigma)
#define CANDCAP   384   // storage cap (holds all threshold ties)
#define SORTN     512

// ---------------- scratch (device globals; no allocation allowed) ----------
__device__ __half g_feath[(size_t)BATCH * DICT_SIZE];  // 256 MB (fp16 coarse feat)
__device__ float  g_Wt[(size_t)DICT_SIZE * ACT_DIM];   // 256 MB (fp32, refine)
__device__ __half g_Wth[(size_t)DICT_SIZE * ACT_DIM];  // 128 MB (fp16: encode B + decode)
__device__ __half g_Ah[(size_t)BATCH * ACT_DIM];       // 16 MB (fp16 x - b_dec)
__device__ int    g_cand_i[(size_t)BATCH * CANDCAP];
__device__ int    g_cand_n[BATCH];
__device__ float  g_topv[(size_t)BATCH * TOPK];
__device__ int    g_topi[(size_t)BATCH * TOPK];

// ---------------- helpers ---------------------------------------------------
__device__ __forceinline__ uint32_t smem_u32(const void* p) {
    uint32_t a;
    asm("{ .reg .u64 t; cvta.to.shared.u64 t, %1; cvt.u32.u64 %0, t; }" : "=r"(a) : "l"(p));
    return a;
}
// XOR swizzle for 128-byte rows (8-row / 1KB atom)
#define SWZ(o) ((o) ^ (((o) >> 3) & 0x70))

__device__ __forceinline__ void cp_async16(uint32_t saddr, const void* gaddr) {
    asm volatile("cp.async.cg.shared.global [%0], [%1], 16;"
                 :: "r"(saddr), "l"(gaddr) : "memory");
}

// ---------------- kernel 0: A = fp16(x - b_dec) ----------------------------
__global__ __launch_bounds__(256)
void convert_x_kernel(const float* __restrict__ x, const float* __restrict__ bdec,
                      __half* __restrict__ Ah) {
    const int row = blockIdx.x;
    const int c0  = threadIdx.x * 8;
    const float* xr = x + (size_t)row * ACT_DIM + c0;
    float4 v1 = *(const float4*)(xr);
    float4 v2 = *(const float4*)(xr + 4);
    float4 b1 = *(const float4*)(bdec + c0);
    float4 b2 = *(const float4*)(bdec + c0 + 4);
    __half2 h0 = __floats2half2_rn(v1.x - b1.x, v1.y - b1.y);
    __half2 h1 = __floats2half2_rn(v1.z - b1.z, v1.w - b1.w);
    __half2 h2 = __floats2half2_rn(v2.x - b2.x, v2.y - b2.y);
    __half2 h3 = __floats2half2_rn(v2.z - b2.z, v2.w - b2.w);
    uint4 out;
    out.x = *(uint32_t*)&h0; out.y = *(uint32_t*)&h1;
    out.z = *(uint32_t*)&h2; out.w = *(uint32_t*)&h3;
    *(uint4*)(Ah + (size_t)row * ACT_DIM + c0) = out;
}

// ---------------- kernel 1: transpose W -> Wt (fp32) + Wth (fp16) ----------
__global__ void transpose_kernel(const float* __restrict__ W, float* __restrict__ Wt,
                                 __half* __restrict__ Wth) {
    __shared__ float tile[32][33];
    const int x0 = blockIdx.x * 32;
    const int y0 = blockIdx.y * 32;
    const int tx = threadIdx.x;
    const int ty = threadIdx.y;
    #pragma unroll
    for (int i = 0; i < 32; i += 8)
        tile[ty + i][tx] = W[(size_t)(y0 + ty + i) * DICT_SIZE + x0 + tx];
    __syncthreads();
    #pragma unroll
    for (int i = 0; i < 32; i += 8) {
        const float v = tile[tx][ty + i];
        const size_t o = (size_t)(x0 + ty + i) * ACT_DIM + y0 + tx;
        Wt[o] = v;
        Wth[o] = __float2half(v);
    }
}

// ---------------- kernel 2: fp16 HMMA encode GEMM (fp32 accumulators) ------
// CTA tile 128x128x64, 8 warps 2Mx4N, 3-stage cp.async ring, 1 barrier/iter.
#define EBM 128
#define EBN 128
#define EBK 64
#define EKITERS (ACT_DIM / EBK)   // 32
#define ESTAGE  32768
#define ENC_SMEM (3 * ESTAGE + 1024)

__global__ __launch_bounds__(256, 2)
void encode_gemm_mma(const __half* __restrict__ Ah,
                     const __half* __restrict__ Bh,
                     __half* __restrict__ feat) {
    extern __shared__ unsigned char dsm[];
    const uint32_t raw  = smem_u32(dsm);
    const uint32_t base = (raw + 1023u) & ~1023u;

    const int tid  = threadIdx.x;
    const int lane = tid & 31;
    const int warp = tid >> 5;
    const int wm   = warp & 1;
    const int wn   = warp >> 1;
    const int Mbase = blockIdx.x * EBM;   // grid.x = M (32)
    const int Nbase = blockIdx.y * EBN;   // grid.y = N (256)

    float acc[4][4][4];
    #pragma unroll
    for (int a = 0; a < 4; a++)
        #pragma unroll
        for (int b = 0; b < 4; b++)
            #pragma unroll
            for (int c = 0; c < 4; c++) acc[a][b][c] = 0.0f;

    const int aRow = wm * 64 + ((lane >> 3) & 1) * 8 + (lane & 7);
    const int ah   = (lane >> 4) & 1;
    const int bRow = wn * 32 + ((lane >> 4) & 1) * 8 + (lane & 7);
    const int bh   = (lane >> 3) & 1;

#define LOAD_STAGE(SLOT, K0)                                                      \
    do {                                                                          \
        const uint32_t aBase = base + (SLOT) * ESTAGE;                            \
        const uint32_t bBase = aBase + 16384u;                                    \
        _Pragma("unroll")                                                         \
        for (int i = 0; i < 4; i++) {                                             \
            const int id = tid + i * 256;                                         \
            const int row = id >> 3, c16 = id & 7;                                \
            cp_async16(aBase + SWZ(row * 128 + c16 * 16),                         \
                       Ah + (size_t)(Mbase + row) * ACT_DIM + (K0) + c16 * 8);    \
        }                                                                         \
        _Pragma("unroll")                                                         \
        for (int i = 0; i < 4; i++) {                                             \
            const int id = tid + i * 256;                                         \
            const int row = id >> 3, c16 = id & 7;                                \
            cp_async16(bBase + SWZ(row * 128 + c16 * 16),                         \
                       Bh + (size_t)(Nbase + row) * ACT_DIM + (K0) + c16 * 8);    \
        }                                                                         \
        asm volatile("cp.async.commit_group;" ::: "memory");                      \
    } while (0)

    LOAD_STAGE(0, 0);
    LOAD_STAGE(1, EBK);

    int slot = 0;
    for (int s = 0; s < EKITERS; s++) {
        if (s + 2 < EKITERS) {
            asm volatile("cp.async.wait_group 1;" ::: "memory");
        } else {
            asm volatile("cp.async.wait_group 0;" ::: "memory");
        }
        __syncthreads();
        if (s + 2 < EKITERS) LOAD_STAGE((slot + 2) % 3, (s + 2) * EBK);

        const uint32_t cA = base + slot * ESTAGE;
        const uint32_t cB = cA + 16384u;

        #pragma unroll
        for (int kk = 0; kk < 4; kk++) {
            uint32_t af[4][4];
            uint32_t bfr[2][4];
            #pragma unroll
            for (int mt = 0; mt < 4; mt++) {
                const uint32_t addr = cA + SWZ((aRow + mt * 16) * 128 + (kk * 2 + ah) * 16);
                asm volatile("ldmatrix.sync.aligned.m8n8.x4.shared.b16 {%0,%1,%2,%3}, [%4];"
                             : "=r"(af[mt][0]), "=r"(af[mt][1]), "=r"(af[mt][2]), "=r"(af[mt][3])
                             : "r"(addr));
            }
            #pragma unroll
            for (int np = 0; np < 2; np++) {
                const uint32_t addr = cB + SWZ((bRow + np * 16) * 128 + (kk * 2 + bh) * 16);
                asm volatile("ldmatrix.sync.aligned.m8n8.x4.shared.b16 {%0,%1,%2,%3}, [%4];"
                             : "=r"(bfr[np][0]), "=r"(bfr[np][1]), "=r"(bfr[np][2]), "=r"(bfr[np][3])
                             : "r"(addr));
            }
            #pragma unroll
            for (int mt = 0; mt < 4; mt++) {
                #pragma unroll
                for (int nt = 0; nt < 4; nt++) {
                    const uint32_t b0 = bfr[nt >> 1][(nt & 1) * 2];
                    const uint32_t b1 = bfr[nt >> 1][(nt & 1) * 2 + 1];
                    asm volatile(
                        "mma.sync.aligned.m16n8k16.row.col.f32.f16.f16.f32 "
                        "{%0,%1,%2,%3}, {%4,%5,%6,%7}, {%8,%9}, {%0,%1,%2,%3};"
                        : "+f"(acc[mt][nt][0]), "+f"(acc[mt][nt][1]),
                          "+f"(acc[mt][nt][2]), "+f"(acc[mt][nt][3])
                        : "r"(af[mt][0]), "r"(af[mt][1]), "r"(af[mt][2]), "r"(af[mt][3]),
                          "r"(b0), "r"(b1));
                }
            }
        }
        slot = (slot + 1) % 3;
    }
#undef LOAD_STAGE

    const int g  = lane >> 2;
    const int tg = lane & 3;
    #pragma unroll
    for (int mt = 0; mt < 4; mt++) {
        #pragma unroll
        for (int nt = 0; nt < 4; nt++) {
            const int r0 = Mbase + wm * 64 + mt * 16 + g;
            const int c  = Nbase + wn * 32 + nt * 8 + tg * 2;
            __half2 p0 = __floats2half2_rn(acc[mt][nt][0], acc[mt][nt][1]);
            __half2 p1 = __floats2half2_rn(acc[mt][nt][2], acc[mt][nt][3]);
            *(uint32_t*)(feat + (size_t)r0 * DICT_SIZE + c)       = *(uint32_t*)&p0;
            *(uint32_t*)(feat + (size_t)(r0 + 8) * DICT_SIZE + c) = *(uint32_t*)&p1;
        }
    }
}

// ---------------- kernel 3: per-row coarse top candidates (streaming radix)
__global__ __launch_bounds__(256)
void topk_kernel(const __half* __restrict__ feat,
                 int* __restrict__ candi, int* __restrict__ candn) {
    __shared__ unsigned int h0[8][128];
    __shared__ unsigned int hist[256];
    __shared__ unsigned int suf[256];
    __shared__ unsigned int sB0, sRem, sThr;
    __shared__ int gcnt, tcnt;
    __shared__ int tiebuf[64];

    const int row  = blockIdx.x;
    const int tid  = threadIdx.x;
    const int warp = tid >> 5;
    const uint4* src = (const uint4*)(feat + (size_t)row * DICT_SIZE);

    {
        unsigned int* hz = &h0[0][0];
        for (int i = tid; i < 8 * 128; i += 256) hz[i] = 0u;
    }
    if (tid == 0) { gcnt = 0; tcnt = 0; }
    __syncthreads();

    for (int i = tid; i < DICT_SIZE / 8; i += 256) {
        const uint4 v = src[i];
        #pragma unroll
        for (int q = 0; q < 4; q++) {
            const unsigned int u = (&v.x)[q];
            atomicAdd(&h0[warp][(u & 0x7FFFu) >> 8], 1u);
            atomicAdd(&h0[warp][((u >> 16) & 0x7FFFu) >> 8], 1u);
        }
    }
    __syncthreads();

    if (tid < 128) {
        unsigned int t = 0;
        #pragma unroll
        for (int w = 0; w < 8; w++) t += h0[w][tid];
        suf[tid] = t;
    }
    __syncthreads();
    for (int off = 1; off < 128; off <<= 1) {
        unsigned int v = 0;
        if (tid < 128 && tid + off < 128) v = suf[tid + off];
        __syncthreads();
        if (tid < 128) suf[tid] += v;
        __syncthreads();
    }
    if (tid < 128) {
        const unsigned int sufNext = (tid == 127) ? 0u : suf[tid + 1];
        if (suf[tid] >= CANDRANK && sufNext < CANDRANK) {
            sB0 = (unsigned int)tid;
            sRem = CANDRANK - sufNext;
        }
    }
    __syncthreads();
    const unsigned int b0sel = sB0;
    const unsigned int rem   = sRem;

    hist[tid] = 0u;
    __syncthreads();
    for (int i = tid; i < DICT_SIZE / 8; i += 256) {
        const uint4 v = src[i];
        #pragma unroll
        for (int q = 0; q < 4; q++) {
            const unsigned int u = (&v.x)[q];
            const unsigned int k0 = u & 0x7FFFu;
            const unsigned int k1 = (u >> 16) & 0x7FFFu;
            if ((k0 >> 8) == b0sel) atomicAdd(&hist[k0 & 255u], 1u);
            if ((k1 >> 8) == b0sel) atomicAdd(&hist[k1 & 255u], 1u);
        }
    }
    __syncthreads();
    suf[tid] = hist[tid];
    __syncthreads();
    for (int off = 1; off < 256; off <<= 1) {
        const unsigned int v = (tid + off < 256) ? suf[tid + off] : 0u;
        __syncthreads();
        suf[tid] += v;
        __syncthreads();
    }
    {
        const unsigned int sufNext = (tid == 255) ? 0u : suf[tid + 1];
        if (suf[tid] >= rem && sufNext < rem)
            sThr = (b0sel << 8) | (unsigned int)tid;
    }
    __syncthreads();
    const unsigned int thr = sThr;

    int* ti = candi + (size_t)row * CANDCAP;
    for (int i = tid; i < DICT_SIZE / 8; i += 256) {
        const uint4 v = src[i];
        #pragma unroll
        for (int q = 0; q < 4; q++) {
            const unsigned int u = (&v.x)[q];
            const unsigned int k0 = u & 0x7FFFu;
            const unsigned int k1 = (u >> 16) & 0x7FFFu;
            if (k0 > thr) {
                const int p = atomicAdd(&gcnt, 1);
                if (p < CANDCAP) ti[p] = i * 8 + q * 2;
            } else if (k0 == thr) {
                const int t = atomicAdd(&tcnt, 1);
                if (t < 64) tiebuf[t] = i * 8 + q * 2;
            }
            if (k1 > thr) {
                const int p = atomicAdd(&gcnt, 1);
                if (p < CANDCAP) ti[p] = i * 8 + q * 2 + 1;
            } else if (k1 == thr) {
                const int t = atomicAdd(&tcnt, 1);
                if (t < 64) tiebuf[t] = i * 8 + q * 2 + 1;
            }
        }
    }
    __syncthreads();
    const int ng = (gcnt < CANDCAP) ? gcnt : CANDCAP;
    const int nt = (tcnt < 64) ? tcnt : 64;
    if (tid < nt && ng + tid < CANDCAP) ti[ng + tid] = tiebuf[tid];
    if (tid == 0) {
        int tot = ng + nt;
        candn[row] = (tot < CANDCAP) ? tot : CANDCAP;
    }
}

// ---------------- kernel 4: fused refine (fp32 Wt) + stable select ---------
// Exact R13 form: single accumulator, #pragma unroll 8 (4-acc full-unroll
// variant regressed in R15 via register pressure).
__global__ __launch_bounds__(512)
void refine_select_kernel(const float* __restrict__ x, const float* __restrict__ bdec,
                          const float* __restrict__ Wt, const int* __restrict__ candi,
                          const int* __restrict__ candn,
                          float* __restrict__ topv, int* __restrict__ topi) {
    __shared__ float sx[ACT_DIM];
    __shared__ int   sci[CANDCAP];
    __shared__ float srv[CANDCAP];
    __shared__ unsigned long long key[SORTN];
    __shared__ float val[SORTN];

    const int row  = blockIdx.x;
    const int tid  = threadIdx.x;     // 0..511
    const int lane = tid & 31;
    const int wid  = tid >> 5;        // 0..15
    const int n    = candn[row];

    const float* xr = x + (size_t)row * ACT_DIM;
    for (int i = tid; i < ACT_DIM; i += 512) sx[i] = xr[i] - bdec[i];
    for (int i = tid; i < CANDCAP; i += 512)
        sci[i] = (i < n) ? candi[(size_t)row * CANDCAP + i] : 0;
    __syncthreads();

    for (int c = wid; c < n; c += 16) {
        const float* wr = Wt + (size_t)sci[c] * ACT_DIM;
        float s = 0.0f;
        #pragma unroll 8
        for (int k = lane; k < ACT_DIM; k += 32)
            s = fmaf(sx[k], wr[k], s);
        #pragma unroll
        for (int off = 16; off > 0; off >>= 1)
            s += __shfl_down_sync(0xffffffffu, s, off);
        if (lane == 0) srv[c] = s;
    }
    __syncthreads();

    {
        const int i = tid;
        if (i < n) {
            const float v = srv[i];
            const unsigned int a = __float_as_uint(fabsf(v));
            key[i] = ((unsigned long long)(~a) << 32) |
                     (unsigned long long)(unsigned int)sci[i];
            val[i] = v;
        } else {
            key[i] = 0xFFFFFFFFFFFFFFFFull;
            val[i] = 0.0f;
        }
    }
    __syncthreads();

    for (int k = 2; k <= SORTN; k <<= 1) {
        for (int j = k >> 1; j > 0; j >>= 1) {
            const int i   = tid;
            const int ixj = i ^ j;
            if (ixj > i) {
                const bool up = ((i & k) == 0);
                const unsigned long long ki = key[i], kj = key[ixj];
                if ((ki > kj) == up) {
                    key[i] = kj; key[ixj] = ki;
                    const float vi = val[i];
                    val[i] = val[ixj]; val[ixj] = vi;
                }
            }
            __syncthreads();
        }
    }

    if (tid < TOPK) {
        topv[(size_t)row * TOPK + tid] = val[tid];
        topi[(size_t)row * TOPK + tid] = (int)(unsigned int)(key[tid] & 0xFFFFFFFFull);
    }
}

// ---------------- kernel 5: sparse gather decode (fp16 W: half traffic) ----
__global__ __launch_bounds__(512)
void decode_kernel(const __half* __restrict__ Wth,
                   const float* __restrict__ topv, const int* __restrict__ topi,
                   const float* __restrict__ bdec, float* __restrict__ out) {
    __shared__ float sval[TOPK];
    __shared__ int   sidx[TOPK];
    const int row = blockIdx.x;
    const int tid = threadIdx.x;   // 0..511

    if (tid < TOPK) {
        sval[tid] = topv[(size_t)row * TOPK + tid];
        sidx[tid] = topi[(size_t)row * TOPK + tid];
    }
    __syncthreads();

    float4 acc = make_float4(0.f, 0.f, 0.f, 0.f);
    const int c = tid * 4;
    #pragma unroll 4
    for (int k = 0; k < TOPK; k++) {
        const float v = sval[k];
        const uint2 w8 = *(const uint2*)(Wth + (size_t)sidx[k] * ACT_DIM + c);
        const __half2 h01 = *(const __half2*)&w8.x;
        const __half2 h23 = *(const __half2*)&w8.y;
        const float2 f01 = __half22float2(h01);
        const float2 f23 = __half22float2(h23);
        acc.x = fmaf(v, f01.x, acc.x);
        acc.y = fmaf(v, f01.y, acc.y);
        acc.z = fmaf(v, f23.x, acc.z);
        acc.w = fmaf(v, f23.y, acc.w);
    }
    const float4 b = *(const float4*)(bdec + c);
    acc.x += b.x; acc.y += b.y; acc.z += b.z; acc.w += b.w;
    *(float4*)(out + (size_t)row * ACT_DIM + c) = acc;
}

// ---------------- launch ---------------------------------------------------
extern "C" void kernel_launch(void* const* d_in, const int* in_sizes, int n_in,
                              void* d_out, int out_size) {
    const float* x    = (const float*)d_in[0];
    const float* W    = (const float*)d_in[1];
    const float* bdec = (const float*)d_in[2];
    float* out = (float*)d_out;

    __half *feath, *Wth, *Ah;
    float *Wt, *topv; int *candi, *candn, *topi;
    cudaGetSymbolAddress((void**)&feath, g_feath);
    cudaGetSymbolAddress((void**)&Wt,    g_Wt);
    cudaGetSymbolAddress((void**)&Wth,   g_Wth);
    cudaGetSymbolAddress((void**)&Ah,    g_Ah);
    cudaGetSymbolAddress((void**)&candi, g_cand_i);
    cudaGetSymbolAddress((void**)&candn, g_cand_n);
    cudaGetSymbolAddress((void**)&topv,  g_topv);
    cudaGetSymbolAddress((void**)&topi,  g_topi);

    convert_x_kernel<<<BATCH, 256>>>(x, bdec, Ah);
    {
        dim3 grid(DICT_SIZE / 32, ACT_DIM / 32);
        dim3 block(32, 8);
        transpose_kernel<<<grid, block>>>(W, Wt, Wth);
    }
    {
        cudaFuncSetAttribute(encode_gemm_mma,
                             cudaFuncAttributeMaxDynamicSharedMemorySize, ENC_SMEM);
        dim3 grid(BATCH / EBM, DICT_SIZE / EBN);   // x = M (32), y = N (256)
        encode_gemm_mma<<<grid, 256, ENC_SMEM>>>(Ah, Wth, feath);
    }
    topk_kernel<<<BATCH, 256>>>(feath, candi, candn);
    refine_select_kernel<<<BATCH, 512>>>(x, bdec, Wt, candi, candn, topv, topi);
    decode_kernel<<<BATCH, 512>>>(Wth, topv, topi, bdec, out);
}